// round 17
// baseline (speedup 1.0000x reference)
#include <cuda_runtime.h>

#define Bv 8
#define Cv 128
#define Hv 128
#define Wv 128
#define KK 9
#define NPLANES (Bv * Cv)
#define N_ITEMS (NPLANES + 4 * NPLANES)   /* 1024 pool + 4096 conv quarters */
#define CONV_CTAS 592   /* 148 SMs x 4 resident */

// Scratch (no allocations allowed in kernel_launch).
// Zero-initialized at module load; self-reset by the exit protocol thereafter.
__device__ float g_pooled[Bv * Cv];
__device__ float g_h[Bv * Cv];
__device__ unsigned int g_ctr;
__device__ unsigned int g_exit;
__device__ unsigned int g_done[Bv];
__device__ volatile unsigned int g_hdone[Bv];

// ---------------------------------------------------------------------------
// Persistent pipelined pool -> h -> kern+conv. Batch-major item order
// (sequential read phase then write phase — R12/R14 proved mixing is toxic).
//   items [0,1024)     : pool plane = item (unrolled-LDG reduce, proven)
//   items [1024,5120)  : t = item-1024; conv plane = t>>2, quarter = t&3
//                        (32 output rows per item -> small end-of-kernel tail)
// Conv: R13 register design (scalar FMA, shfl halo, MLP=4 loads, .cs stores).
// Self-resetting: the last CTA to exit restores all state for the next replay.
// ---------------------------------------------------------------------------
__global__ void __launch_bounds__(256, 4)
mega_kernel(const float* __restrict__ x,
            const float* __restrict__ w1, const float* __restrict__ b1,
            const float* __restrict__ w2, const float* __restrict__ b2,
            float* __restrict__ out) {
    const int tid = threadIdx.x;
    const int wid = tid >> 5;       // 0..7
    const int lane = tid & 31;

    __shared__ unsigned int s_item;
    __shared__ int s_do_h;
    __shared__ float sdata[8];
    __shared__ float kw[KK];

    for (;;) {
        if (tid == 0) s_item = atomicAdd(&g_ctr, 1u);
        __syncthreads();
        const unsigned int item = s_item;
        if (item >= (unsigned)N_ITEMS) break;

        if (item < (unsigned)NPLANES) {
            // ================= POOL (+ maybe h) =================
            const int plane = item;
            const int b = plane >> 7;
            const float4* xp = (const float4*)(x + (size_t)plane * Hv * Wv);

            float sum = 0.f;
#pragma unroll
            for (int i = 0; i < 16; i++) {
                float4 v = xp[tid + i * 256];
                sum += (v.x + v.y) + (v.z + v.w);
            }
#pragma unroll
            for (int o = 16; o; o >>= 1) sum += __shfl_down_sync(0xffffffffu, sum, o);
            if (lane == 0) sdata[wid] = sum;
            __syncthreads();
            if (tid == 0) {
                float t = sdata[0];
#pragma unroll
                for (int i = 1; i < 8; i++) t += sdata[i];
                g_pooled[plane] = t * (1.f / (float)(Hv * Wv));
                __threadfence();
                const unsigned int d = atomicAdd(&g_done[b], 1u);
                s_do_h = (d == Cv - 1);
            }
            __syncthreads();

            if (s_do_h) {
                __threadfence();  // observe all 128 pooled writes
                const float4 pv = __ldcg((const float4*)(g_pooled + b * Cv) + lane);
#pragma unroll 4
                for (int i = 0; i < 16; i++) {
                    const int o = wid * 16 + i;
                    const float4 wv = __ldg((const float4*)(w1 + (size_t)o * Cv) + lane);
                    float acc = wv.x * pv.x;
                    acc = fmaf(wv.y, pv.y, acc);
                    acc = fmaf(wv.z, pv.z, acc);
                    acc = fmaf(wv.w, pv.w, acc);
#pragma unroll
                    for (int s = 16; s; s >>= 1) acc += __shfl_xor_sync(0xffffffffu, acc, s);
                    if (lane == 0) g_h[b * Cv + o] = fmaxf(acc + b1[o], 0.f);
                }
                __syncthreads();
                if (tid == 0) {
                    __threadfence();
                    g_hdone[b] = 1u;   // release flag
                }
            }
        } else {
            // ================= KERN TAPS + CONV (quarter plane) =============
            const unsigned int t = item - NPLANES;
            const int plane = (int)(t >> 2);
            const int quarter = (int)(t & 3u);
            const int b = plane >> 7;
            const int c = plane & 127;

            if (tid == 0) {
                while (g_hdone[b] == 0u) __nanosleep(64);
            }
            __syncthreads();
            __threadfence();  // acquire before g_h reads

            {
                const float4 hv = __ldcg((const float4*)(g_h + b * Cv) + lane);
#pragma unroll
                for (int rep = 0; rep < 2; rep++) {
                    const int p = wid + rep * 8;
                    if (p < KK) {
                        const float4 wv = __ldg((const float4*)(w2 + (size_t)(c * KK + p) * Cv) + lane);
                        float acc = wv.x * hv.x;
                        acc = fmaf(wv.y, hv.y, acc);
                        acc = fmaf(wv.z, hv.z, acc);
                        acc = fmaf(wv.w, hv.w, acc);
#pragma unroll
                        for (int s = 16; s; s >>= 1) acc += __shfl_xor_sync(0xffffffffu, acc, s);
                        if (lane == 0) kw[p] = acc + b2[c * KK + p];
                    }
                }
            }
            __syncthreads();

            float w[9];
#pragma unroll
            for (int p = 0; p < 9; p++) w[p] = kw[p];

            // This warp's 4 output rows within the quarter.
            const int row0 = quarter * 32 + wid * 4;
            const float* xp = x + (size_t)plane * Hv * Wv;
            float* op = out + (size_t)plane * Hv * Wv;

#define LOADF4(v, gr)                                                         \
            {                                                                 \
                if ((gr) < 0 || (gr) >= Hv) { v.x = v.y = v.z = v.w = 0.f; }  \
                else v = __ldg((const float4*)(xp + (gr) * Wv) + lane);       \
            }
#define CONVROW(a, v)                                                         \
            {                                                                 \
                float cm1 = __shfl_up_sync(0xffffffffu, v.w, 1);              \
                float cp4 = __shfl_down_sync(0xffffffffu, v.x, 1);            \
                if (lane == 0) cm1 = 0.f;                                     \
                if (lane == 31) cp4 = 0.f;                                    \
                a[0] = cm1; a[1] = v.x; a[2] = v.y;                           \
                a[3] = v.z; a[4] = v.w; a[5] = cp4;                           \
            }
#define OUTROW(gr, X, Y, Z)                                                   \
            {                                                                 \
                float4 o;                                                     \
                float* po = &o.x;                                             \
                _Pragma("unroll")                                             \
                for (int k = 0; k < 4; k++) {                                 \
                    float acc = X[k] * w[0];                                  \
                    acc = fmaf(X[k + 1], w[1], acc);                          \
                    acc = fmaf(X[k + 2], w[2], acc);                          \
                    acc = fmaf(Y[k],     w[3], acc);                          \
                    acc = fmaf(Y[k + 1], w[4], acc);                          \
                    acc = fmaf(Y[k + 2], w[5], acc);                          \
                    acc = fmaf(Z[k],     w[6], acc);                          \
                    acc = fmaf(Z[k + 1], w[7], acc);                          \
                    acc = fmaf(Z[k + 2], w[8], acc);                          \
                    po[k] = acc;                                              \
                }                                                             \
                __stcs((float4*)(op + (gr) * Wv) + lane, o);                  \
            }

            float A[6], B[6], C[6], D[6], E[6], F[6];
            {
                // Batch all 6 input-row loads up front (MLP = 6).
                float4 v0, v1, p0, p1, p2, p3;
                LOADF4(v0, row0 - 1);
                LOADF4(v1, row0);
                LOADF4(p0, row0 + 1);
                LOADF4(p1, row0 + 2);
                LOADF4(p2, row0 + 3);
                LOADF4(p3, row0 + 4);
                CONVROW(A, v0);
                CONVROW(B, v1);
                CONVROW(C, p0);
                CONVROW(D, p1);
                CONVROW(E, p2);
                CONVROW(F, p3);
            }

            OUTROW(row0 + 0, A, B, C);
            OUTROW(row0 + 1, B, C, D);
            OUTROW(row0 + 2, C, D, E);
            OUTROW(row0 + 3, D, E, F);
#undef LOADF4
#undef CONVROW
#undef OUTROW
        }
    }

    // ---- exit protocol: last CTA out resets all state for the next replay ----
    __syncthreads();
    if (tid == 0) {
        const unsigned int prev = atomicAdd(&g_exit, 1u);
        if (prev == (unsigned)(gridDim.x - 1)) {
#pragma unroll
            for (int i = 0; i < Bv; i++) {
                g_done[i] = 0;
                g_hdone[i] = 0;
            }
            g_ctr = 0;
            __threadfence();
            g_exit = 0;
        }
    }
}

// ---------------------------------------------------------------------------
extern "C" void kernel_launch(void* const* d_in, const int* in_sizes, int n_in,
                              void* d_out, int out_size) {
    const float* x  = (const float*)d_in[0];
    const float* w1 = (const float*)d_in[1];
    const float* b1 = (const float*)d_in[2];
    const float* w2 = (const float*)d_in[3];
    const float* b2 = (const float*)d_in[4];
    float* out = (float*)d_out;

    mega_kernel<<<CONV_CTAS, 256>>>(x, w1, b1, w2, b2, out);
}